// round 16
// baseline (speedup 1.0000x reference)
#include <cuda_runtime.h>
#include <cuda_bf16.h>
#include <cstdint>

// ============================================================================
// AlignmentContrastiveLoss — length-aware packed INT8 mma.sync, persistent CTAs
// R16: meta_kernel DELETED — its table computation is fused into pack_kernel's
//      block 0 (producer), with all other pack blocks spin-gated on g_ready
//      (nanosleep poll + threadfence pairing). mma last-CTA resets the control
//      words (g_ready/g_tick/g_done) after the fused loss so graph replays are
//      deterministic. mma kernel otherwise identical to R15 (105.2us, 3.29e-4).
// ============================================================================

static constexpr int NB  = 128;
static constexpr int DIM = 1024;
static constexpr int MAXMT = 43;
static constexpr int MAXNT = 82;
static constexpr int AROWS = MAXMT * 144;   // 6192
static constexpr int BROWS = MAXNT * 128;   // 10496

static constexpr float QSCALE = 25.0f;
static constexpr float INV2   = 1.0f / (25.0f * 25.0f);

__device__ __align__(16) int8_t g_A[AROWS * DIM];
__device__ __align__(16) int8_t g_B[BROWS * DIM];
__device__ float g_S[NB * NB];

// packing metadata (per-tile segment tables only)
__device__ uint8_t g_colseg[BROWS];            // filled by pack
__device__ int16_t g_tile_b[MAXMT * 36];
__device__ int16_t g_tile_off[MAXMT * 36];
__device__ uint8_t g_tile_len[MAXMT * 36];
__device__ int16_t g_tile_c[MAXNT * 26];
__device__ int16_t g_tile_coff[MAXNT * 26];
__device__ uint8_t g_tile_clen[MAXNT * 26];
__device__ uint8_t g_tile_nb[MAXMT];
__device__ uint8_t g_tile_nc[MAXNT];
__device__ int g_nmt, g_nnt, g_T;
__device__ int g_tick = 0, g_done = 0, g_ready = 0;   // reset by mma tail

// ---------------------------------------------------------------------------
__device__ __forceinline__ uint32_t smem_u32(const void* p) {
    uint32_t a;
    asm("{ .reg .u64 t; cvta.to.shared.u64 t, %1; cvt.u32.u64 %0, t; }" : "=r"(a) : "l"(p));
    return a;
}
__device__ __forceinline__ void cpa16(uint32_t dst, const void* src) {
    asm volatile("cp.async.cg.shared.global [%0], [%1], 16;" :: "r"(dst), "l"(src));
}
#define CPA_COMMIT() asm volatile("cp.async.commit_group;" ::: "memory")
#define CPA_WAIT1()  asm volatile("cp.async.wait_group 1;" ::: "memory")

__device__ __forceinline__ uint32_t lds32(uint32_t a) {
    uint32_t v;
    asm volatile("ld.shared.b32 %0, [%1];" : "=r"(v) : "r"(a));
    return v;
}
__device__ __forceinline__ void mma_s8(int& d0, int& d1, int& d2, int& d3,
                                       uint32_t a0, uint32_t a1, uint32_t a2, uint32_t a3,
                                       uint32_t b0, uint32_t b1) {
    asm volatile(
        "mma.sync.aligned.m16n8k32.row.col.s32.s8.s8.s32 "
        "{%0,%1,%2,%3}, {%4,%5,%6,%7}, {%8,%9}, {%0,%1,%2,%3};"
        : "+r"(d0), "+r"(d1), "+r"(d2), "+r"(d3)
        : "r"(a0), "r"(a1), "r"(a2), "r"(a3), "r"(b0), "r"(b1));
}
__device__ __forceinline__ int q8(float v) {
    return __float2int_rn(fminf(fmaxf(v * QSCALE, -127.f), 127.f));
}

// ---------------------------------------------------------------------------
// Stage 0+1 fused: pack fp32 -> s8. Block 0 produces packing tables (smem
// scans + ~2KB table writes), publishes via g_ready; other blocks spin-gate.
// ---------------------------------------------------------------------------
__global__ void pack_kernel(const float* __restrict__ im, const float* __restrict__ sq,
                            const int* __restrict__ im_len, const int* __restrict__ s_len) {
    const int row = blockIdx.x;
    const int tid = threadIdx.x;

    if (row == 0) {
        // ---- producer: compute packing tables ----
        __shared__ int16_t btile[NB], boff[NB], ctile[NB], coff[NB];
        __shared__ uint8_t bseg[NB], cseg[NB];
        __shared__ int s_iml[NB], s_sl[NB];
        if (tid < NB) s_iml[tid] = im_len[tid];
        else if (tid < 2 * NB) s_sl[tid - NB] = s_len[tid - NB];
        __syncthreads();
        if (tid == 0) {
            int tile = 0, off = 0, seg = 0;
            #pragma unroll 4
            for (int b = 0; b < NB; ++b) {
                int L = s_iml[b] - 1;
                if (off + L > 144) { ++tile; off = 0; seg = 0; }
                btile[b] = (int16_t)tile; boff[b] = (int16_t)off; bseg[b] = (uint8_t)seg;
                off += L; ++seg;
            }
            g_nmt = tile + 1;
        } else if (tid == 64) {
            int tile = 0, off = 0, seg = 0;
            #pragma unroll 4
            for (int c = 0; c < NB; ++c) {
                int L = s_sl[c] - 3;
                if (off + L > 128) { ++tile; off = 0; seg = 0; }
                ctile[c] = (int16_t)tile; coff[c] = (int16_t)off; cseg[c] = (uint8_t)seg;
                off += L; ++seg;
            }
            g_nnt = tile + 1;
        }
        __syncthreads();
        if (tid == 0) g_T = g_nmt * g_nnt;
        if (tid < NB) {
            int b = tid, L = s_iml[b] - 1;
            int tl = btile[b], sg = bseg[b], of = boff[b];
            g_tile_b[tl * 36 + sg]   = (int16_t)b;
            g_tile_off[tl * 36 + sg] = (int16_t)of;
            g_tile_len[tl * 36 + sg] = (uint8_t)L;
            if (b == NB - 1 || btile[b + 1] != tl) g_tile_nb[tl] = (uint8_t)(sg + 1);
        } else if (tid < 2 * NB) {
            int c = tid - NB, L = s_sl[c] - 3;
            int tl = ctile[c], sg = cseg[c], of = coff[c];
            g_tile_c[tl * 26 + sg]    = (int16_t)c;
            g_tile_coff[tl * 26 + sg] = (int16_t)of;
            g_tile_clen[tl * 26 + sg] = (uint8_t)L;
            if (c == NB - 1 || ctile[c + 1] != tl) g_tile_nc[tl] = (uint8_t)(sg + 1);
        }
        __syncthreads();
        __threadfence();
        if (tid == 0) atomicExch(&g_ready, 1);
        // block 0 falls through to pack its own row (row 0)
    } else {
        // ---- consumers: spin-gate on tables ----
        if (tid == 0) {
            while (atomicAdd(&g_ready, 0) == 0) __nanosleep(100);
        }
        __syncthreads();
        __threadfence();
    }

    if (row < 16) {  // zero g_S
        reinterpret_cast<float4*>(g_S)[row * 256 + tid] = make_float4(0.f, 0.f, 0.f, 0.f);
    }

    __shared__ int s_n, s_sel, s_item, s_pos;

    const float* src = nullptr;
    int8_t* dst;
    if (row < AROWS) {
        if (row >= g_nmt * 144) return;
        const int tl = row / 144, local = row - tl * 144;
        if (tid == 0) { s_n = g_tile_nb[tl]; s_sel = -1; }
        __syncthreads();
        if (tid < s_n) {
            int of = g_tile_off[tl * 36 + tid];
            int L  = g_tile_len[tl * 36 + tid];
            if (local >= of && local < of + L) {
                s_item = g_tile_b[tl * 36 + tid];
                s_pos  = local - of;
                s_sel  = tid;
            }
        }
        __syncthreads();
        dst = g_A + (size_t)row * DIM;
        if (s_sel >= 0) src = im + (size_t)(s_item * 37 + s_pos + 1) * DIM;
    } else {
        const int rb = row - AROWS;
        if (rb >= g_nnt * 128) return;
        const int tl = rb / 128, local = rb - tl * 128;
        if (tid == 0) { s_n = g_tile_nc[tl]; s_sel = -1; }
        __syncthreads();
        if (tid < s_n) {
            int of = g_tile_coff[tl * 26 + tid];
            int L  = g_tile_clen[tl * 26 + tid];
            if (local >= of && local < of + L) {
                s_item = g_tile_c[tl * 26 + tid];
                s_pos  = local - of;
                s_sel  = tid;
            }
        }
        __syncthreads();
        dst = g_B + (size_t)rb * DIM;
        if (s_sel >= 0) src = sq + (size_t)(s_item * 53 + s_pos + 1) * DIM;
        if (tid == 0) g_colseg[rb] = (s_sel >= 0) ? (uint8_t)s_sel : 0xFF;
    }
    const int k = tid * 4;
    uint32_t packed = 0u;
    if (src) {
        float4 v = *reinterpret_cast<const float4*>(src + k);
        int q0 = q8(v.x), q1 = q8(v.y), q2 = q8(v.z), q3 = q8(v.w);
        packed = (uint32_t)(q0 & 0xFF) | ((uint32_t)(q1 & 0xFF) << 8) |
                 ((uint32_t)(q2 & 0xFF) << 16) | ((uint32_t)(q3 & 0xFF) << 24);
    }
    *reinterpret_cast<uint32_t*>(dst + k) = packed;
}

// ---------------------------------------------------------------------------
// Stage 2: persistent-CTA s8 GEMM, 3-stage single-sync pipeline, fused loss
// ---------------------------------------------------------------------------
static constexpr int STAGE_BYTES = 21760;
static constexpr int ROW_BYTES   = 80;
static constexpr int B_SM_OFF    = 11520;
static constexpr int SM_RED      = 65280;               // [144][67] f32 = 38592
static constexpr int SM_PAIRS    = 103872;              // [36][26]  f32 = 3744
static constexpr int SM_SEGB     = 107616;              // [36] i16
static constexpr int SM_SEGCL    = 107688;              // [36] u8
static constexpr int SM_SEGOFF   = 107728;              // [36] i16
static constexpr int SM_SEGLEN   = 107800;              // [36] u8
static constexpr int SM_CS       = 107840;              // [64] u8
static constexpr int SM_TIDX     = 107904;              // int
static constexpr int SMEM_TOTAL  = 107968;              // x2 = 215936 < 228K/SM
static constexpr int NCH = 16;
static constexpr int PCTAS = 296;

__global__ __launch_bounds__(384, 2)
void mma_kernel(const int* __restrict__ im_len, const int* __restrict__ s_len,
                float* __restrict__ out) {
    extern __shared__ __align__(16) char sm[];
    const uint32_t sb = smem_u32(sm);
    const int tid  = threadIdx.x;
    const int lane = tid & 31;
    const int wid  = tid >> 5;

    const int wm = wid >> 2;
    const int wn = wid & 3;
    const int group = lane >> 2;
    const int tig   = lane & 3;
    const int mbase = wm * 48;
    const int nbase = wn * 32;

    const int nnt = g_nnt;
    const int T   = g_T;
    int* s_t = reinterpret_cast<int*>(sm + SM_TIDX);

    // stage: 0..2 ring; chunk k lives in stage k%3
    auto load_stage = [&](int stage, int chunk, const int8_t* Ap, const int8_t* Bp) {
        const int k0 = chunk * 64;
        const uint32_t base = sb + stage * STAGE_BYTES;
        #pragma unroll
        for (int it = 0; it < 3; ++it) {
            int idx = tid + it * 384;
            if (idx < 576) {
                int row = idx >> 2, seg = idx & 3;
                cpa16(base + row * ROW_BYTES + seg * 16, Ap + row * DIM + k0 + seg * 16);
            } else if (idx < 1088) {
                int u = idx - 576;
                int row = u >> 2, seg = u & 3;
                cpa16(base + B_SM_OFF + row * ROW_BYTES + seg * 16, Bp + row * DIM + k0 + seg * 16);
            }
        }
    };

    // first ticket + prologue loads (chunks 0,1 into stages 0,1)
    if (tid == 0) *s_t = atomicAdd(&g_tick, 1);
    __syncthreads();
    int t = *s_t;
    if (t < T) {
        const int mt0 = t / nnt, nt0 = t - (t / nnt) * nnt;
        const int8_t* Ap = g_A + (size_t)mt0 * (144 * DIM);
        const int8_t* Bp = g_B + (size_t)nt0 * (128 * DIM);
        load_stage(0, 0, Ap, Bp); CPA_COMMIT();
        load_stage(1, 1, Ap, Bp); CPA_COMMIT();
    }

    while (t < T) {
        const int mt = t / nnt;
        const int nt = t - mt * nnt;
        const int8_t* Ap = g_A + (size_t)mt * (144 * DIM);
        const int8_t* Bp = g_B + (size_t)nt * (128 * DIM);

        int acc[3][4][4];
        #pragma unroll
        for (int mi = 0; mi < 3; ++mi)
            #pragma unroll
            for (int ni = 0; ni < 4; ++ni)
                #pragma unroll
                for (int q = 0; q < 4; ++q) acc[mi][ni][q] = 0;

        // 3-stage single-sync mainloop
        for (int ch = 0; ch < NCH; ++ch) {
            CPA_WAIT1();
            __syncthreads();
            if (ch + 2 < NCH) { load_stage((ch + 2) % 3, ch + 2, Ap, Bp); CPA_COMMIT(); }
            const uint32_t As = sb + (ch % 3) * STAGE_BYTES;
            const uint32_t Bs = As + B_SM_OFF;
            #pragma unroll
            for (int kk = 0; kk < 2; ++kk) {
                const uint32_t kb = kk * 32;
                uint32_t a[3][4];
                #pragma unroll
                for (int mi = 0; mi < 3; ++mi) {
                    uint32_t r0 = As + (mbase + mi * 16 + group) * ROW_BYTES + kb + tig * 4;
                    uint32_t r1 = r0 + 8 * ROW_BYTES;
                    a[mi][0] = lds32(r0);
                    a[mi][1] = lds32(r1);
                    a[mi][2] = lds32(r0 + 16);
                    a[mi][3] = lds32(r1 + 16);
                }
                #pragma unroll
                for (int ni = 0; ni < 4; ++ni) {
                    uint32_t rb = Bs + (nbase + ni * 8 + group) * ROW_BYTES + kb + tig * 4;
                    uint32_t b0 = lds32(rb);
                    uint32_t b1 = lds32(rb + 16);
                    #pragma unroll
                    for (int mi = 0; mi < 3; ++mi)
                        mma_s8(acc[mi][ni][0], acc[mi][ni][1], acc[mi][ni][2], acc[mi][ni][3],
                               a[mi][0], a[mi][1], a[mi][2], a[mi][3], b0, b1);
                }
            }
        }
        __syncthreads();   // all warps done reading stages for this tile

        // fetch next ticket and prefetch its chunks 0,1 BEFORE epilogue
        if (tid == 0) *s_t = atomicAdd(&g_tick, 1);
        __syncthreads();
        const int t2 = *s_t;
        if (t2 < T) {
            const int mt2 = t2 / nnt, nt2 = t2 - (t2 / nnt) * nnt;
            const int8_t* Ap2 = g_A + (size_t)mt2 * (144 * DIM);
            const int8_t* Bp2 = g_B + (size_t)nt2 * (128 * DIM);
            load_stage(0, 0, Ap2, Bp2); CPA_COMMIT();
            load_stage(1, 1, Ap2, Bp2); CPA_COMMIT();
        }

        // ---------------- epilogue (red region disjoint from stages) -------
        float*   red    = reinterpret_cast<float*>(sm + SM_RED);
        float*   pairS  = reinterpret_cast<float*>(sm + SM_PAIRS);
        int16_t* segb   = reinterpret_cast<int16_t*>(sm + SM_SEGB);
        uint8_t* segcl  = reinterpret_cast<uint8_t*>(sm + SM_SEGCL);
        int16_t* segoff = reinterpret_cast<int16_t*>(sm + SM_SEGOFF);
        uint8_t* seglen = reinterpret_cast<uint8_t*>(sm + SM_SEGLEN);
        uint8_t* cs_sm  = reinterpret_cast<uint8_t*>(sm + SM_CS);

        const int nbv = g_tile_nb[mt];
        for (int i = tid; i < 36 * 26; i += 384) pairS[i] = 0.f;
        if (tid < nbv) {
            int s = tid;
            segb[s]   = g_tile_b[mt * 36 + s];
            segoff[s] = g_tile_off[mt * 36 + s];
            int L = g_tile_len[mt * 36 + s];
            seglen[s] = (uint8_t)L;
            segcl[s]  = (L < 36) ? 1 : 0;
        }

        #pragma unroll
        for (int h = 0; h < 2; ++h) {
            if (tid < 64) cs_sm[tid] = g_colseg[nt * 128 + h * 64 + tid];
            __syncthreads();
            if ((wn >> 1) == h) {
                #pragma unroll
                for (int mi = 0; mi < 3; ++mi)
                    #pragma unroll
                    for (int half = 0; half < 2; ++half) {
                        const int r = mbase + mi * 16 + group + half * 8;
                        #pragma unroll
                        for (int ni = 0; ni < 4; ++ni) {
                            int col = nbase + ni * 8 + tig * 2 - h * 64;
                            red[r * 67 + col]     = (float)acc[mi][ni][half * 2 + 0] * INV2;
                            red[r * 67 + col + 1] = (float)acc[mi][ni][half * 2 + 1] * INV2;
                        }
                    }
            }
            __syncthreads();

            const int col = tid & 63;
            const int cs = cs_sm[col];
            if (cs != 0xFF) {
                for (int s = tid >> 6; s < nbv; s += 6) {
                    const int r0 = segoff[s];
                    const int L  = seglen[s];
                    const float* cp = red + r0 * 67 + col;
                    float m = cp[0];
                    for (int r = 1; r < L; ++r) m = fmaxf(m, cp[r * 67]);
                    if (segcl[s]) m = fmaxf(m, 0.f);
                    atomicAdd(&pairS[s * 26 + cs], m);
                }
            }
            __syncthreads();
        }

        const int ncv = g_tile_nc[nt];
        for (int idx = tid; idx < nbv * ncv; idx += 384) {
            int s = idx / ncv, cs = idx - s * ncv;
            int b = segb[s];
            int c = g_tile_c[nt * 26 + cs];
            g_S[b * NB + c] = pairS[s * 26 + cs];
        }
        __syncthreads();
        t = t2;
    }

    // ---------------- fused loss: last CTA reduces g_S + resets control ----
    __threadfence();
    __syncthreads();
    if (tid == 0) {
        int old = atomicAdd(&g_done, 1);
        *s_t = (old == PCTAS - 1) ? 1 : 0;
    }
    __syncthreads();
    if (*s_t) {
        __threadfence();
        float* diag = reinterpret_cast<float*>(sm);
        float* wsum = reinterpret_cast<float*>(sm) + 128;
        if (tid < NB) diag[tid] = g_S[tid * (NB + 1)];
        __syncthreads();
        float acc = 0.f;
        for (int idx = tid; idx < NB * NB; idx += 384) {
            int b = idx >> 7, c = idx & 127;
            if (b != c) {
                float sc = g_S[idx];
                acc += fmaxf(0.f, 0.2f + sc - diag[b]) + fmaxf(0.f, 0.2f + sc - diag[c]);
            }
        }
        #pragma unroll
        for (int o = 16; o; o >>= 1) acc += __shfl_xor_sync(0xffffffffu, acc, o);
        if (lane == 0) wsum[wid] = acc;
        __syncthreads();
        if (wid == 0) {
            float v = (lane < 12) ? wsum[lane] : 0.f;
            #pragma unroll
            for (int o = 16; o; o >>= 1) v += __shfl_xor_sync(0xffffffffu, v, o);
            if (lane == 0) out[0] = v;
        }
        // reset control words for the next graph replay (deterministic re-derive)
        if (tid == 0) { g_tick = 0; g_done = 0; g_ready = 0; }
    }
}

// ---------------------------------------------------------------------------
extern "C" void kernel_launch(void* const* d_in, const int* in_sizes, int n_in,
                              void* d_out, int out_size) {
    (void)in_sizes; (void)n_in; (void)out_size;
    const float* im   = (const float*)d_in[0];
    const float* sq   = (const float*)d_in[1];
    const int* im_len = (const int*)d_in[2];
    const int* s_len  = (const int*)d_in[3];

    cudaFuncSetAttribute(mma_kernel, cudaFuncAttributeMaxDynamicSharedMemorySize, SMEM_TOTAL);

    pack_kernel<<<AROWS + BROWS, 256>>>(im, sq, im_len, s_len);
    mma_kernel<<<PCTAS, 384, SMEM_TOTAL>>>(im_len, s_len, (float*)d_out);
}

// round 17
// speedup vs baseline: 1.1139x; 1.1139x over previous
#include <cuda_runtime.h>
#include <cuda_bf16.h>
#include <cstdint>

// ============================================================================
// AlignmentContrastiveLoss — length-aware packed INT8 mma.sync, persistent CTAs
// R17: revert R16's pack fusion (cost 11.5us). R15 3-kernel structure +
//      ldmatrix fragment loads: per-kk 20x LDS.32 -> 3x ldmatrix.x4 + 4x .x2
//      (issue count -35%, 4x data per instruction). Profile showed mma is
//      dependency-bound (tensor 24%, L1 36%, issue 36%), not pipe-bound.
// ============================================================================

static constexpr int NB  = 128;
static constexpr int DIM = 1024;
static constexpr int MAXMT = 43;
static constexpr int MAXNT = 82;
static constexpr int AROWS = MAXMT * 144;   // 6192
static constexpr int BROWS = MAXNT * 128;   // 10496

static constexpr float QSCALE = 25.0f;
static constexpr float INV2   = 1.0f / (25.0f * 25.0f);

__device__ __align__(16) int8_t g_A[AROWS * DIM];
__device__ __align__(16) int8_t g_B[BROWS * DIM];
__device__ float g_S[NB * NB];

// packing metadata (per-tile segment tables only)
__device__ uint8_t g_colseg[BROWS];            // filled by pack
__device__ int16_t g_tile_b[MAXMT * 36];
__device__ int16_t g_tile_off[MAXMT * 36];
__device__ uint8_t g_tile_len[MAXMT * 36];
__device__ int16_t g_tile_c[MAXNT * 26];
__device__ int16_t g_tile_coff[MAXNT * 26];
__device__ uint8_t g_tile_clen[MAXNT * 26];
__device__ uint8_t g_tile_nb[MAXMT];
__device__ uint8_t g_tile_nc[MAXNT];
__device__ int g_nmt, g_nnt, g_T, g_tick, g_done;

// ---------------------------------------------------------------------------
__device__ __forceinline__ uint32_t smem_u32(const void* p) {
    uint32_t a;
    asm("{ .reg .u64 t; cvta.to.shared.u64 t, %1; cvt.u32.u64 %0, t; }" : "=r"(a) : "l"(p));
    return a;
}
__device__ __forceinline__ void cpa16(uint32_t dst, const void* src) {
    asm volatile("cp.async.cg.shared.global [%0], [%1], 16;" :: "r"(dst), "l"(src));
}
#define CPA_COMMIT() asm volatile("cp.async.commit_group;" ::: "memory")
#define CPA_WAIT1()  asm volatile("cp.async.wait_group 1;" ::: "memory")

__device__ __forceinline__ void ldsm_x4(uint32_t& r0, uint32_t& r1, uint32_t& r2, uint32_t& r3,
                                        uint32_t a) {
    asm volatile("ldmatrix.sync.aligned.m8n8.x4.shared.b16 {%0,%1,%2,%3}, [%4];"
                 : "=r"(r0), "=r"(r1), "=r"(r2), "=r"(r3) : "r"(a));
}
__device__ __forceinline__ void ldsm_x2(uint32_t& r0, uint32_t& r1, uint32_t a) {
    asm volatile("ldmatrix.sync.aligned.m8n8.x2.shared.b16 {%0,%1}, [%2];"
                 : "=r"(r0), "=r"(r1) : "r"(a));
}
__device__ __forceinline__ void mma_s8(int& d0, int& d1, int& d2, int& d3,
                                       uint32_t a0, uint32_t a1, uint32_t a2, uint32_t a3,
                                       uint32_t b0, uint32_t b1) {
    asm volatile(
        "mma.sync.aligned.m16n8k32.row.col.s32.s8.s8.s32 "
        "{%0,%1,%2,%3}, {%4,%5,%6,%7}, {%8,%9}, {%0,%1,%2,%3};"
        : "+r"(d0), "+r"(d1), "+r"(d2), "+r"(d3)
        : "r"(a0), "r"(a1), "r"(a2), "r"(a3), "r"(b0), "r"(b1));
}
__device__ __forceinline__ int q8(float v) {
    return __float2int_rn(fminf(fmaxf(v * QSCALE, -127.f), 127.f));
}

// ---------------------------------------------------------------------------
// Stage 0: metadata — serial smem scans + O(1)-per-thread table writes (~2KB)
// ---------------------------------------------------------------------------
__global__ void meta_kernel(const int* __restrict__ im_len, const int* __restrict__ s_len) {
    __shared__ int16_t btile[NB], boff[NB], ctile[NB], coff[NB];
    __shared__ uint8_t bseg[NB], cseg[NB];
    __shared__ int s_iml[NB], s_sl[NB];
    const int tid = threadIdx.x;

    if (tid < NB) s_iml[tid] = im_len[tid];
    else if (tid < 2 * NB) s_sl[tid - NB] = s_len[tid - NB];
    if (tid == 32) { g_tick = 0; g_done = 0; }
    __syncthreads();

    if (tid == 0) {
        int tile = 0, off = 0, seg = 0;
        #pragma unroll 4
        for (int b = 0; b < NB; ++b) {
            int L = s_iml[b] - 1;
            if (off + L > 144) { ++tile; off = 0; seg = 0; }
            btile[b] = (int16_t)tile; boff[b] = (int16_t)off; bseg[b] = (uint8_t)seg;
            off += L; ++seg;
        }
        g_nmt = tile + 1;
    } else if (tid == 64) {
        int tile = 0, off = 0, seg = 0;
        #pragma unroll 4
        for (int c = 0; c < NB; ++c) {
            int L = s_sl[c] - 3;
            if (off + L > 128) { ++tile; off = 0; seg = 0; }
            ctile[c] = (int16_t)tile; coff[c] = (int16_t)off; cseg[c] = (uint8_t)seg;
            off += L; ++seg;
        }
        g_nnt = tile + 1;
    }
    __syncthreads();
    if (tid == 0) g_T = g_nmt * g_nnt;

    if (tid < NB) {
        int b = tid, L = s_iml[b] - 1;
        int tl = btile[b], sg = bseg[b], of = boff[b];
        g_tile_b[tl * 36 + sg]   = (int16_t)b;
        g_tile_off[tl * 36 + sg] = (int16_t)of;
        g_tile_len[tl * 36 + sg] = (uint8_t)L;
        if (b == NB - 1 || btile[b + 1] != tl) g_tile_nb[tl] = (uint8_t)(sg + 1);
    } else if (tid < 2 * NB) {
        int c = tid - NB, L = s_sl[c] - 3;
        int tl = ctile[c], sg = cseg[c], of = coff[c];
        g_tile_c[tl * 26 + sg]    = (int16_t)c;
        g_tile_coff[tl * 26 + sg] = (int16_t)of;
        g_tile_clen[tl * 26 + sg] = (uint8_t)L;
        if (c == NB - 1 || ctile[c + 1] != tl) g_tile_nc[tl] = (uint8_t)(sg + 1);
    }
}

// ---------------------------------------------------------------------------
// Stage 1: pack fp32 -> s8; each block resolves its row via segment match
// ---------------------------------------------------------------------------
__global__ void pack_kernel(const float* __restrict__ im, const float* __restrict__ sq) {
    const int row = blockIdx.x;
    const int tid = threadIdx.x;

    if (row < 16) {  // zero g_S
        reinterpret_cast<float4*>(g_S)[row * 256 + tid] = make_float4(0.f, 0.f, 0.f, 0.f);
    }

    __shared__ int s_n, s_sel, s_item, s_pos;

    const float* src = nullptr;
    int8_t* dst;
    if (row < AROWS) {
        if (row >= g_nmt * 144) return;
        const int tl = row / 144, local = row - tl * 144;
        if (tid == 0) { s_n = g_tile_nb[tl]; s_sel = -1; }
        __syncthreads();
        if (tid < s_n) {
            int of = g_tile_off[tl * 36 + tid];
            int L  = g_tile_len[tl * 36 + tid];
            if (local >= of && local < of + L) {
                s_item = g_tile_b[tl * 36 + tid];
                s_pos  = local - of;
                s_sel  = tid;
            }
        }
        __syncthreads();
        dst = g_A + (size_t)row * DIM;
        if (s_sel >= 0) src = im + (size_t)(s_item * 37 + s_pos + 1) * DIM;
    } else {
        const int rb = row - AROWS;
        if (rb >= g_nnt * 128) return;
        const int tl = rb / 128, local = rb - tl * 128;
        if (tid == 0) { s_n = g_tile_nc[tl]; s_sel = -1; }
        __syncthreads();
        if (tid < s_n) {
            int of = g_tile_coff[tl * 26 + tid];
            int L  = g_tile_clen[tl * 26 + tid];
            if (local >= of && local < of + L) {
                s_item = g_tile_c[tl * 26 + tid];
                s_pos  = local - of;
                s_sel  = tid;
            }
        }
        __syncthreads();
        dst = g_B + (size_t)rb * DIM;
        if (s_sel >= 0) src = sq + (size_t)(s_item * 53 + s_pos + 1) * DIM;
        if (tid == 0) g_colseg[rb] = (s_sel >= 0) ? (uint8_t)s_sel : 0xFF;
    }
    const int k = tid * 4;
    uint32_t packed = 0u;
    if (src) {
        float4 v = *reinterpret_cast<const float4*>(src + k);
        int q0 = q8(v.x), q1 = q8(v.y), q2 = q8(v.z), q3 = q8(v.w);
        packed = (uint32_t)(q0 & 0xFF) | ((uint32_t)(q1 & 0xFF) << 8) |
                 ((uint32_t)(q2 & 0xFF) << 16) | ((uint32_t)(q3 & 0xFF) << 24);
    }
    *reinterpret_cast<uint32_t*>(dst + k) = packed;
}

// ---------------------------------------------------------------------------
// Stage 2: persistent-CTA s8 GEMM, 3-stage pipeline, ldmatrix, fused loss
// ---------------------------------------------------------------------------
static constexpr int STAGE_BYTES = 21760;
static constexpr int ROW_BYTES   = 80;
static constexpr int B_SM_OFF    = 11520;
static constexpr int SM_RED      = 65280;               // [144][67] f32 = 38592
static constexpr int SM_PAIRS    = 103872;              // [36][26]  f32 = 3744
static constexpr int SM_SEGB     = 107616;              // [36] i16
static constexpr int SM_SEGCL    = 107688;              // [36] u8
static constexpr int SM_SEGOFF   = 107728;              // [36] i16
static constexpr int SM_SEGLEN   = 107800;              // [36] u8
static constexpr int SM_CS       = 107840;              // [64] u8
static constexpr int SM_TIDX     = 107904;              // int
static constexpr int SMEM_TOTAL  = 107968;              // x2 = 215936 < 228K/SM
static constexpr int NCH = 16;
static constexpr int PCTAS = 296;

__global__ __launch_bounds__(384, 2)
void mma_kernel(const int* __restrict__ im_len, const int* __restrict__ s_len,
                float* __restrict__ out) {
    extern __shared__ __align__(16) char sm[];
    const uint32_t sb = smem_u32(sm);
    const int tid  = threadIdx.x;
    const int lane = tid & 31;
    const int wid  = tid >> 5;

    const int wm = wid >> 2;
    const int wn = wid & 3;
    const int group = lane >> 2;
    const int tig   = lane & 3;
    const int mbase = wm * 48;
    const int nbase = wn * 32;

    // ldmatrix lane->address offsets (relative to stage base)
    //  A x4: row = mbase + mi*16 + (lane&15), byte = kb + (lane>>4)*16
    //  B x2: row = nbase + ni*8 + (lane&7),  byte = kb + ((lane>>3)&1)*16
    const uint32_t a_lds = (uint32_t)(mbase + (lane & 15)) * ROW_BYTES + ((lane >> 4) << 4);
    const uint32_t b_lds = (uint32_t)B_SM_OFF +
                           (uint32_t)(nbase + (lane & 7)) * ROW_BYTES + (((lane >> 3) & 1) << 4);

    const int nnt = g_nnt;
    const int T   = g_T;
    int* s_t = reinterpret_cast<int*>(sm + SM_TIDX);

    auto load_stage = [&](int stage, int chunk, const int8_t* Ap, const int8_t* Bp) {
        const int k0 = chunk * 64;
        const uint32_t base = sb + stage * STAGE_BYTES;
        #pragma unroll
        for (int it = 0; it < 3; ++it) {
            int idx = tid + it * 384;
            if (idx < 576) {
                int row = idx >> 2, seg = idx & 3;
                cpa16(base + row * ROW_BYTES + seg * 16, Ap + row * DIM + k0 + seg * 16);
            } else if (idx < 1088) {
                int u = idx - 576;
                int row = u >> 2, seg = u & 3;
                cpa16(base + B_SM_OFF + row * ROW_BYTES + seg * 16, Bp + row * DIM + k0 + seg * 16);
            }
        }
    };

    // first ticket + prologue loads (chunks 0,1 into stages 0,1)
    if (tid == 0) *s_t = atomicAdd(&g_tick, 1);
    __syncthreads();
    int t = *s_t;
    if (t < T) {
        const int mt0 = t / nnt, nt0 = t - (t / nnt) * nnt;
        const int8_t* Ap = g_A + (size_t)mt0 * (144 * DIM);
        const int8_t* Bp = g_B + (size_t)nt0 * (128 * DIM);
        load_stage(0, 0, Ap, Bp); CPA_COMMIT();
        load_stage(1, 1, Ap, Bp); CPA_COMMIT();
    }

    while (t < T) {
        const int mt = t / nnt;
        const int nt = t - mt * nnt;
        const int8_t* Ap = g_A + (size_t)mt * (144 * DIM);
        const int8_t* Bp = g_B + (size_t)nt * (128 * DIM);

        int acc[3][4][4];
        #pragma unroll
        for (int mi = 0; mi < 3; ++mi)
            #pragma unroll
            for (int ni = 0; ni < 4; ++ni)
                #pragma unroll
                for (int q = 0; q < 4; ++q) acc[mi][ni][q] = 0;

        // 3-stage single-sync mainloop, ldmatrix fragment loads
        for (int ch = 0; ch < NCH; ++ch) {
            CPA_WAIT1();
            __syncthreads();
            if (ch + 2 < NCH) { load_stage((ch + 2) % 3, ch + 2, Ap, Bp); CPA_COMMIT(); }
            const uint32_t As = sb + (ch % 3) * STAGE_BYTES;
            #pragma unroll
            for (int kk = 0; kk < 2; ++kk) {
                const uint32_t kb = kk * 32;
                uint32_t a[3][4];
                #pragma unroll
                for (int mi = 0; mi < 3; ++mi)
                    ldsm_x4(a[mi][0], a[mi][1], a[mi][2], a[mi][3],
                            As + a_lds + mi * (16 * ROW_BYTES) + kb);
                #pragma unroll
                for (int ni = 0; ni < 4; ++ni) {
                    uint32_t b0, b1;
                    ldsm_x2(b0, b1, As + b_lds + ni * (8 * ROW_BYTES) + kb);
                    #pragma unroll
                    for (int mi = 0; mi < 3; ++mi)
                        mma_s8(acc[mi][ni][0], acc[mi][ni][1], acc[mi][ni][2], acc[mi][ni][3],
                               a[mi][0], a[mi][1], a[mi][2], a[mi][3], b0, b1);
                }
            }
        }
        __syncthreads();   // all warps done reading stages for this tile

        // fetch next ticket and prefetch its chunks 0,1 BEFORE epilogue
        if (tid == 0) *s_t = atomicAdd(&g_tick, 1);
        __syncthreads();
        const int t2 = *s_t;
        if (t2 < T) {
            const int mt2 = t2 / nnt, nt2 = t2 - (t2 / nnt) * nnt;
            const int8_t* Ap2 = g_A + (size_t)mt2 * (144 * DIM);
            const int8_t* Bp2 = g_B + (size_t)nt2 * (128 * DIM);
            load_stage(0, 0, Ap2, Bp2); CPA_COMMIT();
            load_stage(1, 1, Ap2, Bp2); CPA_COMMIT();
        }

        // ---------------- epilogue (red region disjoint from stages) -------
        float*   red    = reinterpret_cast<float*>(sm + SM_RED);
        float*   pairS  = reinterpret_cast<float*>(sm + SM_PAIRS);
        int16_t* segb   = reinterpret_cast<int16_t*>(sm + SM_SEGB);
        uint8_t* segcl  = reinterpret_cast<uint8_t*>(sm + SM_SEGCL);
        int16_t* segoff = reinterpret_cast<int16_t*>(sm + SM_SEGOFF);
        uint8_t* seglen = reinterpret_cast<uint8_t*>(sm + SM_SEGLEN);
        uint8_t* cs_sm  = reinterpret_cast<uint8_t*>(sm + SM_CS);

        const int nbv = g_tile_nb[mt];
        for (int i = tid; i < 36 * 26; i += 384) pairS[i] = 0.f;
        if (tid < nbv) {
            int s = tid;
            segb[s]   = g_tile_b[mt * 36 + s];
            segoff[s] = g_tile_off[mt * 36 + s];
            int L = g_tile_len[mt * 36 + s];
            seglen[s] = (uint8_t)L;
            segcl[s]  = (L < 36) ? 1 : 0;
        }

        #pragma unroll
        for (int h = 0; h < 2; ++h) {
            if (tid < 64) cs_sm[tid] = g_colseg[nt * 128 + h * 64 + tid];
            __syncthreads();
            if ((wn >> 1) == h) {
                #pragma unroll
                for (int mi = 0; mi < 3; ++mi)
                    #pragma unroll
                    for (int half = 0; half < 2; ++half) {
                        const int r = mbase + mi * 16 + group + half * 8;
                        #pragma unroll
                        for (int ni = 0; ni < 4; ++ni) {
                            int col = nbase + ni * 8 + tig * 2 - h * 64;
                            red[r * 67 + col]     = (float)acc[mi][ni][half * 2 + 0] * INV2;
                            red[r * 67 + col + 1] = (float)acc[mi][ni][half * 2 + 1] * INV2;
                        }
                    }
            }
            __syncthreads();

            const int col = tid & 63;
            const int cs = cs_sm[col];
            if (cs != 0xFF) {
                for (int s = tid >> 6; s < nbv; s += 6) {
                    const int r0 = segoff[s];
                    const int L  = seglen[s];
                    const float* cp = red + r0 * 67 + col;
                    float m = cp[0];
                    for (int r = 1; r < L; ++r) m = fmaxf(m, cp[r * 67]);
                    if (segcl[s]) m = fmaxf(m, 0.f);
                    atomicAdd(&pairS[s * 26 + cs], m);
                }
            }
            __syncthreads();
        }

        const int ncv = g_tile_nc[nt];
        for (int idx = tid; idx < nbv * ncv; idx += 384) {
            int s = idx / ncv, cs = idx - s * ncv;
            int b = segb[s];
            int c = g_tile_c[nt * 26 + cs];
            g_S[b * NB + c] = pairS[s * 26 + cs];
        }
        __syncthreads();
        t = t2;
    }

    // ---------------- fused loss: last CTA reduces g_S ----------------
    __threadfence();
    __syncthreads();
    if (tid == 0) {
        int old = atomicAdd(&g_done, 1);
        *s_t = (old == PCTAS - 1) ? 1 : 0;
    }
    __syncthreads();
    if (*s_t) {
        __threadfence();
        float* diag = reinterpret_cast<float*>(sm);
        float* wsum = reinterpret_cast<float*>(sm) + 128;
        if (tid < NB) diag[tid] = g_S[tid * (NB + 1)];
        __syncthreads();
        float acc = 0.f;
        for (int idx = tid; idx < NB * NB; idx += 384) {
            int b = idx >> 7, c = idx & 127;
            if (b != c) {
                float sc = g_S[idx];
                acc += fmaxf(0.f, 0.2f + sc - diag[b]) + fmaxf(0.f, 0.2f + sc - diag[c]);
            }
        }
        #pragma unroll
        for (int o = 16; o; o >>= 1) acc += __shfl_xor_sync(0xffffffffu, acc, o);
        if (lane == 0) wsum[wid] = acc;
        __syncthreads();
        if (wid == 0) {
            float v = (lane < 12) ? wsum[lane] : 0.f;
            #pragma unroll
            for (int o = 16; o; o >>= 1) v += __shfl_xor_sync(0xffffffffu, v, o);
            if (lane == 0) out[0] = v;
        }
    }
}

// ---------------------------------------------------------------------------
extern "C" void kernel_launch(void* const* d_in, const int* in_sizes, int n_in,
                              void* d_out, int out_size) {
    (void)in_sizes; (void)n_in; (void)out_size;
    const float* im   = (const float*)d_in[0];
    const float* sq   = (const float*)d_in[1];
    const int* im_len = (const int*)d_in[2];
    const int* s_len  = (const int*)d_in[3];

    cudaFuncSetAttribute(mma_kernel, cudaFuncAttributeMaxDynamicSharedMemorySize, SMEM_TOTAL);

    meta_kernel<<<1, 256>>>(im_len, s_len);
    pack_kernel<<<AROWS + BROWS, 256>>>(im, sq);
    mma_kernel<<<PCTAS, 384, SMEM_TOTAL>>>(im_len, s_len, (float*)d_out);
}